// round 3
// baseline (speedup 1.0000x reference)
#include <cuda_runtime.h>
#include <math.h>

// ---------------------------------------------------------------------------
// Bregman divergence via 1-D function tabulation.
// div(y,y0) = F(y) - F(y0) - G(y0)*dy + 0.5*a*dy^2
//             + c*( y*(log(max(y,1e-10)) - log(max(y0,1e-10))) - dy )
// F(x) = sum_j v_j * (H_j(x) - H_j(0)),  G(x) = sum_j v_j * act_j(w_j x + b_j)
// ---------------------------------------------------------------------------

#define TN     2048
#define NGRP   21
#define NNEUR  126
#define EPSF   1e-3f

__device__ float2 g_node[TN + 1];   // (F, G) at node i

// ---------------- fused precompute: constants + node eval -------------------
// Each 64-thread block: compute the 126 per-neuron constants into smem
// (threads 0..63 each do 2 neurons), then each thread evaluates one node
// across all 126 neurons. 33 blocks cover 2049 nodes.
__global__ void precompute_kernel(const float* __restrict__ v,
                                  const float* __restrict__ w,
                                  const float* __restrict__ b) {
    __shared__ float4 sA[NNEUR];   // (w, b_or_B, k, kb)
    __shared__ float2 sB[NNEUR];   // (v, small_flag)

    for (int j = threadIdx.x; j < NNEUR; j += blockDim.x) {
        int grp = j / NGRP;
        float wj = w[j], bj = b[j], vj = v[j];
        bool  small = fabsf(wj) < 1e-12f;
        float rw = 1.0f / (small ? 1.0f : wj);

        float k = 0.0f, kb = 0.0f, b2 = bj;
        if (grp == 0) { k = 0.25f * vj * rw; kb = k * bj * bj * bj * bj; }
        else if (grp == 1) { k = vj * rw * (1.0f / 3.0f); kb = k * bj * bj * bj; }
        else if (grp == 2) { float bc = fmaxf(bj, 0.0f); k = (2.0f / 3.0f) * vj * rw;
                             kb = k * bc * sqrtf(bc); }
        else if (grp == 3) { float bc = fmaxf(bj, 0.0f); k = 0.75f * vj * rw;
                             kb = k * bc * cbrtf(bc); }
        else if (grp == 4) { float B = fmaxf(bj, 0.0f) + EPSF; b2 = B; k = vj * B * rw; }
        else               { k = vj * expf(bj); }

        sA[j] = make_float4(wj, b2, k, kb);
        sB[j] = make_float2(vj, small ? 1.0f : 0.0f);
    }
    __syncthreads();

    int node = blockIdx.x * blockDim.x + threadIdx.x;
    if (node > TN) return;
    float x = (float)node * (1.0f / (float)TN);

    float accF = 0.0f, accG = 0.0f;

    // group 0: act=u^3
    #pragma unroll
    for (int t = 0; t < NGRP; t++) {
        float4 cA = sA[t]; float2 cB = sB[t];
        float u = fmaf(cA.x, x, cA.y);
        float u2 = u * u;
        float h = fmaf(cA.z, u2 * u2, -cA.w);
        float va = cB.x * (u2 * u);
        accG += va;
        accF += (cB.y != 0.0f) ? va * x : h;
    }
    // group 1: act=u^2
    #pragma unroll
    for (int t = 0; t < NGRP; t++) {
        float4 cA = sA[NGRP + t]; float2 cB = sB[NGRP + t];
        float u = fmaf(cA.x, x, cA.y);
        float u2 = u * u;
        float h = fmaf(cA.z, u2 * u, -cA.w);
        float va = cB.x * u2;
        accG += va;
        accF += (cB.y != 0.0f) ? va * x : h;
    }
    // group 2: act=sqrt(u+)
    #pragma unroll
    for (int t = 0; t < NGRP; t++) {
        float4 cA = sA[2 * NGRP + t]; float2 cB = sB[2 * NGRP + t];
        float u = fmaf(cA.x, x, cA.y);
        float uc = fmaxf(u, 0.0f);
        float s = sqrtf(uc);
        float h = fmaf(cA.z, uc * s, -cA.w);
        float va = cB.x * s;
        accG += va;
        accF += (cB.y != 0.0f) ? va * x : h;
    }
    // group 3: act=u+^(1/3)
    #pragma unroll
    for (int t = 0; t < NGRP; t++) {
        float4 cA = sA[3 * NGRP + t]; float2 cB = sB[3 * NGRP + t];
        float u = fmaf(cA.x, x, cA.y);
        float uc = fmaxf(u, 0.0f);
        float cb = cbrtf(uc);
        float h = fmaf(cA.z, uc * cb, -cA.w);
        float va = cB.x * cb;
        accG += va;
        accF += (cB.y != 0.0f) ? va * x : h;
    }
    // group 4: act=log(u+ + eps);  cA.y=B=b+eps, cA.z=v*B/w
    #pragma unroll
    for (int t = 0; t < NGRP; t++) {
        float4 cA = sA[4 * NGRP + t]; float2 cB = sB[4 * NGRP + t];
        float u = fmaf(cA.x, x, cA.y - EPSF);
        float U = fmaxf(u, 0.0f) + EPSF;
        float lu = logf(U);
        float z = cA.x * x / cA.y;
        float h = fmaf(cB.x * x, lu - 1.0f, cA.z * log1pf(z));
        float va = cB.x * lu;
        accG += va;
        accF += (cB.y != 0.0f) ? va * x : h;
    }
    // group 5: act=exp(u);  cA.z=v*exp(b); Taylor in t=w*x (|t|<=0.01)
    #pragma unroll
    for (int t = 0; t < NGRP; t++) {
        float4 cA = sA[5 * NGRP + t]; float2 cB = sB[5 * NGRP + t];
        float t1 = cA.x * x;
        float E1 = 1.0f + t1 * (1.0f + t1 * (0.5f + t1 * ((1.0f / 6.0f) + t1 * (1.0f / 24.0f))));
        float P  = 1.0f + t1 * (0.5f + t1 * ((1.0f / 6.0f)
                       + t1 * ((1.0f / 24.0f) + t1 * (1.0f / 120.0f))));
        float va = cA.z * E1;
        accG += va;
        accF += (cB.y != 0.0f) ? va * x : cA.z * x * P;
    }

    g_node[node] = make_float2(accF, accG);
}

// ------------------------------- main kernel --------------------------------
__device__ __forceinline__ float bregman_elem(float y, float y0, float a, float c,
                                              const float4* __restrict__ tab) {
    float ty = y * (float)TN;
    int   iy = (int)ty; iy = min(max(iy, 0), TN - 1);
    float fy = ty - (float)iy;
    float2 ey = *(const float2*)(tab + iy);      // only F half needed for y
    float Fy = fmaf(fy, ey.y, ey.x);

    float t0 = y0 * (float)TN;
    int   i0 = (int)t0; i0 = min(max(i0, 0), TN - 1);
    float f0 = t0 - (float)i0;
    float4 e0 = tab[i0];
    float F0 = fmaf(f0, e0.y, e0.x);
    float G0 = fmaf(f0, e0.w, e0.z);

    float dy = y - y0;
    float d  = Fy - F0;
    d = fmaf(-G0, dy, d);
    d = fmaf(0.5f * a * dy, dy, d);

    float ys  = fmaxf(y,  1e-10f);
    float y0s = fmaxf(y0, 1e-10f);
    float kl  = fmaf(y, __logf(ys) - __logf(y0s), -dy);
    d = fmaf(c, kl, d);
    return d;
}

__global__ __launch_bounds__(256, 6)
void main_kernel(const float4* __restrict__ Y, const float4* __restrict__ Y0,
                 const float* __restrict__ A, const float* __restrict__ C,
                 float4* __restrict__ OUT, int n4) {
    __shared__ float4 tab[TN];   // (F0, dF, G0, dG) : 32 KB
    for (int i = threadIdx.x; i < TN; i += blockDim.x) {
        float2 n0 = g_node[i];
        float2 n1 = g_node[i + 1];
        tab[i] = make_float4(n0.x, n1.x - n0.x, n0.y, n1.y - n0.y);
    }
    __syncthreads();

    float a = __ldg(A);
    float c = __ldg(C);
    int stride = gridDim.x * blockDim.x;
    for (int idx = blockIdx.x * blockDim.x + threadIdx.x; idx < n4; idx += stride) {
        float4 yv  = __ldg(Y  + idx);
        float4 y0v = __ldg(Y0 + idx);
        float4 o;
        o.x = bregman_elem(yv.x, y0v.x, a, c, tab);
        o.y = bregman_elem(yv.y, y0v.y, a, c, tab);
        o.z = bregman_elem(yv.z, y0v.z, a, c, tab);
        o.w = bregman_elem(yv.w, y0v.w, a, c, tab);
        OUT[idx] = o;
    }
}

// scalar tail (n % 4): reads g_node directly (tiny, usually not launched)
__global__ void tail_kernel(const float* __restrict__ Y, const float* __restrict__ Y0,
                            const float* __restrict__ A, const float* __restrict__ C,
                            float* __restrict__ OUT, int start, int n) {
    int i = start + blockIdx.x * blockDim.x + threadIdx.x;
    if (i >= n) return;
    float y = Y[i], y0 = Y0[i];
    float a = __ldg(A), c = __ldg(C);

    float ty = y * (float)TN;
    int   iy = (int)ty; iy = min(max(iy, 0), TN - 1);
    float fy = ty - (float)iy;
    float2 n0 = g_node[iy], n1 = g_node[iy + 1];
    float Fy = fmaf(fy, n1.x - n0.x, n0.x);

    float t0 = y0 * (float)TN;
    int   i0 = (int)t0; i0 = min(max(i0, 0), TN - 1);
    float f0 = t0 - (float)i0;
    float2 m0 = g_node[i0], m1 = g_node[i0 + 1];
    float F0 = fmaf(f0, m1.x - m0.x, m0.x);
    float G0 = fmaf(f0, m1.y - m0.y, m0.y);

    float dy = y - y0;
    float d  = Fy - F0;
    d = fmaf(-G0, dy, d);
    d = fmaf(0.5f * a * dy, dy, d);
    float ys  = fmaxf(y,  1e-10f);
    float y0s = fmaxf(y0, 1e-10f);
    float kl  = fmaf(y, __logf(ys) - __logf(y0s), -dy);
    OUT[i] = fmaf(c, kl, d);
}

// ------------------------------- launch -------------------------------------
extern "C" void kernel_launch(void* const* d_in, const int* in_sizes, int n_in,
                              void* d_out, int out_size) {
    const float* y  = (const float*)d_in[0];
    const float* y0 = (const float*)d_in[1];
    const float* v  = (const float*)d_in[2];
    const float* w  = (const float*)d_in[3];
    const float* b  = (const float*)d_in[4];
    const float* a  = (const float*)d_in[5];
    const float* c  = (const float*)d_in[6];

    // one fused precompute launch: 33 blocks x 64 threads cover 2049 nodes
    precompute_kernel<<<(TN + 1 + 63) / 64, 64>>>(v, w, b);

    int n  = out_size;
    int n4 = n >> 2;
    if (n4 > 0)
        main_kernel<<<888, 256>>>((const float4*)y, (const float4*)y0,
                                  a, c, (float4*)d_out, n4);
    int rem = n & 3;
    if (rem)
        tail_kernel<<<1, 32>>>(y, y0, a, c, (float*)d_out, n4 << 2, n);
}

// round 4
// speedup vs baseline: 1.1248x; 1.1248x over previous
#include <cuda_runtime.h>
#include <math.h>

// ---------------------------------------------------------------------------
// Bregman divergence via 1-D tabulation with the log folded into the table:
//   Py(x) = F(x) + c*x*log(max(x,1e-10))
//   Gp(x) = G(x) + c
//   div   = Py(y) - Py(y0) - (Gp(y0) + c*log(max(y0,1e-10)))*dy + 0.5*a*dy^2
// where F(x) = sum_j v_j*(H_j(x)-H_j(0)),  G(x) = sum_j v_j*act_j(w_j x+b_j).
// Only ONE __logf per element (MUFU was the saturated pipe in R3).
// ---------------------------------------------------------------------------

#define TN     2048
#define NGRP   21
#define NNEUR  126
#define EPSF   1e-3f

__device__ float2 g_part[6 * (TN + 1)];  // per-group (F,G) partials
__device__ float2 g_node[TN + 1];        // (Py, Gp) at node i

// ---------------- node partials: grid (17, 6) x 128 threads -----------------
__global__ void node_kernel(const float* __restrict__ v,
                            const float* __restrict__ w,
                            const float* __restrict__ b) {
    int g = blockIdx.y;
    __shared__ float4 sA[NGRP];   // (w, b_or_B, k, kb)
    __shared__ float2 sB[NGRP];   // (v, small_flag)

    if (threadIdx.x < NGRP) {
        int j = g * NGRP + threadIdx.x;
        float wj = w[j], bj = b[j], vj = v[j];
        bool  small = fabsf(wj) < 1e-12f;
        float rw = 1.0f / (small ? 1.0f : wj);

        float k = 0.0f, kb = 0.0f, b2 = bj;
        if (g == 0) { k = 0.25f * vj * rw; kb = k * bj * bj * bj * bj; }
        else if (g == 1) { k = vj * rw * (1.0f / 3.0f); kb = k * bj * bj * bj; }
        else if (g == 2) { float bc = fmaxf(bj, 0.0f); k = (2.0f / 3.0f) * vj * rw;
                           kb = k * bc * sqrtf(bc); }
        else if (g == 3) { float bc = fmaxf(bj, 0.0f); k = 0.75f * vj * rw;
                           kb = k * bc * cbrtf(bc); }
        else if (g == 4) { float B = fmaxf(bj, 0.0f) + EPSF; b2 = B; k = vj * B * rw; }
        else             { k = vj * expf(bj); }

        sA[threadIdx.x] = make_float4(wj, b2, k, kb);
        sB[threadIdx.x] = make_float2(vj, small ? 1.0f : 0.0f);
    }
    __syncthreads();

    int node = blockIdx.x * blockDim.x + threadIdx.x;
    if (node > TN) return;
    float x = (float)node * (1.0f / (float)TN);

    float accF = 0.0f, accG = 0.0f;

    if (g == 0) {                         // act = u^3, H = u^4/(4w)
        #pragma unroll
        for (int t = 0; t < NGRP; t++) {
            float4 cA = sA[t]; float2 cB = sB[t];
            float u = fmaf(cA.x, x, cA.y);
            float u2 = u * u;
            float h = fmaf(cA.z, u2 * u2, -cA.w);
            float va = cB.x * (u2 * u);
            accG += va;
            accF += (cB.y != 0.0f) ? va * x : h;
        }
    } else if (g == 1) {                  // act = u^2
        #pragma unroll
        for (int t = 0; t < NGRP; t++) {
            float4 cA = sA[t]; float2 cB = sB[t];
            float u = fmaf(cA.x, x, cA.y);
            float u2 = u * u;
            float h = fmaf(cA.z, u2 * u, -cA.w);
            float va = cB.x * u2;
            accG += va;
            accF += (cB.y != 0.0f) ? va * x : h;
        }
    } else if (g == 2) {                  // act = sqrt(u+)
        #pragma unroll
        for (int t = 0; t < NGRP; t++) {
            float4 cA = sA[t]; float2 cB = sB[t];
            float u = fmaf(cA.x, x, cA.y);
            float uc = fmaxf(u, 0.0f);
            float s = sqrtf(uc);
            float h = fmaf(cA.z, uc * s, -cA.w);
            float va = cB.x * s;
            accG += va;
            accF += (cB.y != 0.0f) ? va * x : h;
        }
    } else if (g == 3) {                  // act = u+^(1/3)
        #pragma unroll
        for (int t = 0; t < NGRP; t++) {
            float4 cA = sA[t]; float2 cB = sB[t];
            float u = fmaf(cA.x, x, cA.y);
            float uc = fmaxf(u, 0.0f);
            float cb = cbrtf(uc);
            float h = fmaf(cA.z, uc * cb, -cA.w);
            float va = cB.x * cb;
            accG += va;
            accF += (cB.y != 0.0f) ? va * x : h;
        }
    } else if (g == 4) {                  // act = log(u+ + eps); cA.y=B, cA.z=v*B/w
        #pragma unroll
        for (int t = 0; t < NGRP; t++) {
            float4 cA = sA[t]; float2 cB = sB[t];
            float u = fmaf(cA.x, x, cA.y - EPSF);
            float U = fmaxf(u, 0.0f) + EPSF;
            float lu = logf(U);
            float z = cA.x * x / cA.y;
            float h = fmaf(cB.x * x, lu - 1.0f, cA.z * log1pf(z));
            float va = cB.x * lu;
            accG += va;
            accF += (cB.y != 0.0f) ? va * x : h;
        }
    } else {                              // act = exp(u); cA.z=v*e^b; |w x|<=0.01
        #pragma unroll
        for (int t = 0; t < NGRP; t++) {
            float4 cA = sA[t]; float2 cB = sB[t];
            float t1 = cA.x * x;
            float E1 = 1.0f + t1 * (1.0f + t1 * (0.5f + t1 * ((1.0f / 6.0f) + t1 * (1.0f / 24.0f))));
            float P  = 1.0f + t1 * (0.5f + t1 * ((1.0f / 6.0f)
                           + t1 * ((1.0f / 24.0f) + t1 * (1.0f / 120.0f))));
            float va = cA.z * E1;
            accG += va;
            accF += (cB.y != 0.0f) ? va * x : cA.z * x * P;
        }
    }
    g_part[g * (TN + 1) + node] = make_float2(accF, accG);
}

// ------------- combine partials + fold c-terms (exact node logs) ------------
__global__ void combine_kernel(const float* __restrict__ C) {
    int i = blockIdx.x * blockDim.x + threadIdx.x;
    if (i > TN) return;
    float F = 0.0f, G = 0.0f;
    #pragma unroll
    for (int g = 0; g < 6; g++) {
        float2 p = g_part[g * (TN + 1) + i];
        F += p.x; G += p.y;
    }
    float c = __ldg(C);
    float x = (float)i * (1.0f / (float)TN);
    float Py = fmaf(c * x, logf(fmaxf(x, 1e-10f)), F);
    g_node[i] = make_float2(Py, G + c);
}

// ------------------------------- main kernel --------------------------------
__device__ __forceinline__ float bregman_elem(float y, float y0, float a, float c,
                                              const float4* __restrict__ tab) {
    float ty = y * (float)TN;
    int   iy = min((int)ty, TN - 1);
    float fy = ty - (float)iy;
    float2 ey = *(const float2*)(tab + iy);      // (Py, dPy)
    float PY = fmaf(fy, ey.y, ey.x);

    float t0 = y0 * (float)TN;
    int   i0 = min((int)t0, TN - 1);
    float f0 = t0 - (float)i0;
    float4 e0 = tab[i0];                         // (Py, dPy, Gp, dGp)
    float P0 = fmaf(f0, e0.y, e0.x);
    float G0 = fmaf(f0, e0.w, e0.z);

    float dy = y - y0;
    float L0 = __logf(fmaxf(y0, 1e-10f));
    float slope = fmaf(c, L0, G0);               // G + c + c*L0
    float d = PY - P0;
    d = fmaf(-slope, dy, d);
    d = fmaf(0.5f * a * dy, dy, d);
    return d;
}

__global__ __launch_bounds__(256, 6)
void main_kernel(const float4* __restrict__ Y, const float4* __restrict__ Y0,
                 const float* __restrict__ A, const float* __restrict__ C,
                 float4* __restrict__ OUT, int n4) {
    __shared__ float4 tab[TN];   // (Py0, dPy, Gp0, dGp) : 32 KB
    for (int i = threadIdx.x; i < TN; i += blockDim.x) {
        float2 n0 = g_node[i];
        float2 n1 = g_node[i + 1];
        tab[i] = make_float4(n0.x, n1.x - n0.x, n0.y, n1.y - n0.y);
    }
    __syncthreads();

    float a = __ldg(A);
    float c = __ldg(C);
    int stride = gridDim.x * blockDim.x;
    for (int idx = blockIdx.x * blockDim.x + threadIdx.x; idx < n4; idx += stride) {
        float4 yv  = __ldg(Y  + idx);
        float4 y0v = __ldg(Y0 + idx);
        float4 o;
        o.x = bregman_elem(yv.x, y0v.x, a, c, tab);
        o.y = bregman_elem(yv.y, y0v.y, a, c, tab);
        o.z = bregman_elem(yv.z, y0v.z, a, c, tab);
        o.w = bregman_elem(yv.w, y0v.w, a, c, tab);
        OUT[idx] = o;
    }
}

// scalar tail (n % 4): reads g_node directly (not launched when n%4==0)
__global__ void tail_kernel(const float* __restrict__ Y, const float* __restrict__ Y0,
                            const float* __restrict__ A, const float* __restrict__ C,
                            float* __restrict__ OUT, int start, int n) {
    int i = start + blockIdx.x * blockDim.x + threadIdx.x;
    if (i >= n) return;
    float y = Y[i], y0 = Y0[i];
    float a = __ldg(A), c = __ldg(C);

    float ty = y * (float)TN;
    int   iy = min((int)ty, TN - 1);
    float fy = ty - (float)iy;
    float2 n0 = g_node[iy], n1 = g_node[iy + 1];
    float PY = fmaf(fy, n1.x - n0.x, n0.x);

    float t0 = y0 * (float)TN;
    int   i0 = min((int)t0, TN - 1);
    float f0 = t0 - (float)i0;
    float2 m0 = g_node[i0], m1 = g_node[i0 + 1];
    float P0 = fmaf(f0, m1.x - m0.x, m0.x);
    float G0 = fmaf(f0, m1.y - m0.y, m0.y);

    float dy = y - y0;
    float L0 = logf(fmaxf(y0, 1e-10f));
    float d = PY - P0;
    d = fmaf(-fmaf(c, L0, G0), dy, d);
    d = fmaf(0.5f * a * dy, dy, d);
    OUT[i] = d;
}

// ------------------------------- launch -------------------------------------
extern "C" void kernel_launch(void* const* d_in, const int* in_sizes, int n_in,
                              void* d_out, int out_size) {
    const float* y  = (const float*)d_in[0];
    const float* y0 = (const float*)d_in[1];
    const float* v  = (const float*)d_in[2];
    const float* w  = (const float*)d_in[3];
    const float* b  = (const float*)d_in[4];
    const float* a  = (const float*)d_in[5];
    const float* c  = (const float*)d_in[6];

    dim3 ngrid((TN + 1 + 127) / 128, 6);
    node_kernel<<<ngrid, 128>>>(v, w, b);
    combine_kernel<<<(TN + 1 + 127) / 128, 128>>>(c);

    int n  = out_size;
    int n4 = n >> 2;
    if (n4 > 0)
        main_kernel<<<888, 256>>>((const float4*)y, (const float4*)y0,
                                  a, c, (float4*)d_out, n4);
    int rem = n & 3;
    if (rem)
        tail_kernel<<<1, 32>>>(y, y0, a, c, (float*)d_out, n4 << 2, n);
}

// round 5
// speedup vs baseline: 1.4221x; 1.2643x over previous
#include <cuda_runtime.h>
#include <math.h>

// ---------------------------------------------------------------------------
// Bregman divergence via 1-D tabulation with the KL log folded into the table:
//   Py(x) = F(x) + c*x*log(max(x,1e-10))
//   Gp(x) = G(x) + c
//   div   = Py(y) - Py(y0) - (Gp(y0) + c*log(max(y0,1e-10)))*dy + 0.5*a*dy^2
// F(x) = sum_j v_j*(H_j(x)-H_j(0)),  G(x) = sum_j v_j*act_j(w_j x+b_j).
// ---------------------------------------------------------------------------

#define TN     2048
#define NGRP   21
#define NNEUR  126
#define EPSF   1e-3f

__device__ float2 g_node[TN + 1];   // (Py, Gp) at node i

// -------- precompute: one block per node, one THREAD per neuron -------------
// Critical path per thread = ONE transcendental (R4's 21-deep serial loop was
// the 9.2us bottleneck). Deterministic shfl_xor + smem reduction.
__global__ __launch_bounds__(128)
void node_kernel(const float* __restrict__ v,
                 const float* __restrict__ w,
                 const float* __restrict__ b,
                 const float* __restrict__ C) {
    int node = blockIdx.x;                       // 0..TN
    int j = threadIdx.x;                         // 0..127 (126 neurons)
    float x = (float)node * (1.0f / (float)TN);

    float accF = 0.0f, accG = 0.0f;
    if (j < NNEUR) {
        int g = j / NGRP;
        float wj = __ldg(w + j), bj = __ldg(b + j), vj = __ldg(v + j);
        bool  small = fabsf(wj) < 1e-12f;
        float rw = 1.0f / (small ? 1.0f : wj);
        float u  = fmaf(wj, x, bj);

        float act, hh;
        if (g == 0) {                            // act=u^3, H=u^4/(4w)
            float u2 = u * u;
            act = u2 * u;
            float b2 = bj * bj;
            hh = (u2 * u2 - b2 * b2) * (0.25f * rw);
        } else if (g == 1) {                     // act=u^2, H=u^3/(3w)
            float u2 = u * u;
            act = u2;
            hh = (u2 * u - bj * bj * bj) * (rw * (1.0f / 3.0f));
        } else if (g == 2) {                     // act=sqrt(u+), H=(2/3)u+^1.5/w
            float uc = fmaxf(u, 0.0f);
            float s  = sqrtf(uc);
            act = s;
            float bc = fmaxf(bj, 0.0f);
            hh = (2.0f / 3.0f) * rw * (uc * s - bc * sqrtf(bc));
        } else if (g == 3) {                     // act=u+^(1/3), H=0.75 u+^(4/3)/w
            float uc = fmaxf(u, 0.0f);
            float cb = cbrtf(uc);
            act = cb;
            float bc = fmaxf(bj, 0.0f);
            hh = 0.75f * rw * (uc * cb - bc * cbrtf(bc));
        } else if (g == 4) {                     // act=log(u+ + eps)
            float U  = fmaxf(u, 0.0f) + EPSF;
            float lu = logf(U);
            act = lu;
            if (u >= 0.0f && bj >= 0.0f) {
                // (U(lnU-1)-B(lnB-1))/w == x(lnU-1) + (B/w) log1p(w x/B)
                float B = bj + EPSF;
                hh = fmaf(x, lu - 1.0f, (B * rw) * log1pf(wj * x / B));
            } else {
                float B  = fmaxf(bj, 0.0f) + EPSF;
                float lb = logf(B);
                hh = (U * (lu - 1.0f) - B * (lb - 1.0f)) * rw;
            }
        } else {                                 // act=exp(u), H=exp(u)/w
            float e = expf(u);
            act = e;
            // (e^u - e^b)/w = e^b * x * (1 + t/2 + t^2/6 + t^3/24 + t^4/120)
            float t = wj * x;
            float P = 1.0f + t * (0.5f + t * ((1.0f / 6.0f)
                          + t * ((1.0f / 24.0f) + t * (1.0f / 120.0f))));
            hh = expf(bj) * x * P;
        }
        accG = vj * act;
        accF = small ? accG * x : vj * hh;
    }

    // deterministic warp bfly reduce, then 4-warp smem combine
    #pragma unroll
    for (int s = 16; s > 0; s >>= 1) {
        accF += __shfl_xor_sync(0xFFFFFFFFu, accF, s);
        accG += __shfl_xor_sync(0xFFFFFFFFu, accG, s);
    }
    __shared__ float2 part[4];
    if ((j & 31) == 0) part[j >> 5] = make_float2(accF, accG);
    __syncthreads();
    if (j == 0) {
        float F = part[0].x + part[1].x + part[2].x + part[3].x;
        float G = part[0].y + part[1].y + part[2].y + part[3].y;
        float c = __ldg(C);
        float Py = fmaf(c * x, logf(fmaxf(x, 1e-10f)), F);
        g_node[node] = make_float2(Py, G + c);
    }
}

// ------------------------------- main kernel --------------------------------
__device__ __forceinline__ float bregman_elem(float y, float y0, float a, float c,
                                              const float4* __restrict__ tab) {
    float ty = y * (float)TN;
    int   iy = min((int)ty, TN - 1);
    float fy = ty - (float)iy;
    float2 ey = *(const float2*)(tab + iy);      // (Py, dPy)
    float PY = fmaf(fy, ey.y, ey.x);

    float t0 = y0 * (float)TN;
    int   i0 = min((int)t0, TN - 1);
    float f0 = t0 - (float)i0;
    float4 e0 = tab[i0];                         // (Py, dPy, Gp, dGp)
    float P0 = fmaf(f0, e0.y, e0.x);
    float G0 = fmaf(f0, e0.w, e0.z);

    float dy = y - y0;
    float L0 = __logf(fmaxf(y0, 1e-10f));
    float slope = fmaf(c, L0, G0);               // G + c + c*log(y0s)
    float d = PY - P0;
    d = fmaf(-slope, dy, d);
    d = fmaf(0.5f * a * dy, dy, d);
    return d;
}

__global__ __launch_bounds__(256, 6)
void main_kernel(const float4* __restrict__ Y, const float4* __restrict__ Y0,
                 const float* __restrict__ A, const float* __restrict__ C,
                 float4* __restrict__ OUT, int n4) {
    __shared__ float4 tab[TN];   // (Py0, dPy, Gp0, dGp) : 32 KB
    for (int i = threadIdx.x; i < TN; i += blockDim.x) {
        float2 n0 = g_node[i];
        float2 n1 = g_node[i + 1];
        tab[i] = make_float4(n0.x, n1.x - n0.x, n0.y, n1.y - n0.y);
    }
    __syncthreads();

    float a = __ldg(A);
    float c = __ldg(C);
    int stride = gridDim.x * blockDim.x;
    for (int idx = blockIdx.x * blockDim.x + threadIdx.x; idx < n4; idx += stride) {
        float4 yv  = __ldg(Y  + idx);
        float4 y0v = __ldg(Y0 + idx);
        float4 o;
        o.x = bregman_elem(yv.x, y0v.x, a, c, tab);
        o.y = bregman_elem(yv.y, y0v.y, a, c, tab);
        o.z = bregman_elem(yv.z, y0v.z, a, c, tab);
        o.w = bregman_elem(yv.w, y0v.w, a, c, tab);
        OUT[idx] = o;
    }
}

// scalar tail (n % 4): reads g_node directly (not launched when n%4==0)
__global__ void tail_kernel(const float* __restrict__ Y, const float* __restrict__ Y0,
                            const float* __restrict__ A, const float* __restrict__ C,
                            float* __restrict__ OUT, int start, int n) {
    int i = start + blockIdx.x * blockDim.x + threadIdx.x;
    if (i >= n) return;
    float y = Y[i], y0 = Y0[i];
    float a = __ldg(A), c = __ldg(C);

    float ty = y * (float)TN;
    int   iy = min((int)ty, TN - 1);
    float fy = ty - (float)iy;
    float2 n0 = g_node[iy], n1 = g_node[iy + 1];
    float PY = fmaf(fy, n1.x - n0.x, n0.x);

    float t0 = y0 * (float)TN;
    int   i0 = min((int)t0, TN - 1);
    float f0 = t0 - (float)i0;
    float2 m0 = g_node[i0], m1 = g_node[i0 + 1];
    float P0 = fmaf(f0, m1.x - m0.x, m0.x);
    float G0 = fmaf(f0, m1.y - m0.y, m0.y);

    float dy = y - y0;
    float L0 = logf(fmaxf(y0, 1e-10f));
    float d = PY - P0;
    d = fmaf(-fmaf(c, L0, G0), dy, d);
    d = fmaf(0.5f * a * dy, dy, d);
    OUT[i] = d;
}

// ------------------------------- launch -------------------------------------
extern "C" void kernel_launch(void* const* d_in, const int* in_sizes, int n_in,
                              void* d_out, int out_size) {
    const float* y  = (const float*)d_in[0];
    const float* y0 = (const float*)d_in[1];
    const float* v  = (const float*)d_in[2];
    const float* w  = (const float*)d_in[3];
    const float* b  = (const float*)d_in[4];
    const float* a  = (const float*)d_in[5];
    const float* c  = (const float*)d_in[6];

    // single precompute launch: one block per node, one thread per neuron
    node_kernel<<<TN + 1, 128>>>(v, w, b, c);

    int n  = out_size;
    int n4 = n >> 2;
    if (n4 > 0)
        main_kernel<<<888, 256>>>((const float4*)y, (const float4*)y0,
                                  a, c, (float4*)d_out, n4);
    int rem = n & 3;
    if (rem)
        tail_kernel<<<1, 32>>>(y, y0, a, c, (float*)d_out, n4 << 2, n);
}